// round 1
// baseline (speedup 1.0000x reference)
#include <cuda_runtime.h>
#include <cuda_bf16.h>

// Problem dims (fixed by the reference)
#define BB 16
#define TT 512     // text tokens
#define AA 4096    // audio frames
#define DD 256     // hidden dim
#define CHUNKS 64  // a-chunks per batch
#define A_PER (AA / CHUNKS)  // 64 audio frames per block

// Scratch: W[b][t] = sum_a softmax weights. No cudaMalloc allowed -> device global.
__device__ float g_W[BB * TT];

__global__ void zero_W_kernel() {
    g_W[blockIdx.x * blockDim.x + threadIdx.x] = 0.0f;
}

// Kernel 1: accumulate softmax weights over audio frames into g_W.
// Grid: BB*CHUNKS blocks of 256 threads (8 warps). One warp owns one audio
// frame per iteration; each lane owns 16 tokens (t = lane + 32k).
__global__ __launch_bounds__(256) void softmax_acc_kernel(
    const float* __restrict__ centers,      // [B, T]
    const float* __restrict__ audio_ts)     // [B, A]
{
    const int b     = blockIdx.x / CHUNKS;
    const int chunk = blockIdx.x % CHUNKS;
    const int tid   = threadIdx.x;
    const int lane  = tid & 31;
    const int warp  = tid >> 5;

    __shared__ float sc[TT];     // centers for this batch
    __shared__ float sWacc[TT];  // per-block W partial

    for (int i = tid; i < TT; i += 256) {
        sc[i] = centers[b * TT + i];
        sWacc[i] = 0.0f;
    }
    __syncthreads();

    // Per-lane token subset in registers
    float c[16];
#pragma unroll
    for (int k = 0; k < 16; k++) c[k] = sc[lane + 32 * k];

    float acc[16];
#pragma unroll
    for (int k = 0; k < 16; k++) acc[k] = 0.0f;

    const int a0 = chunk * A_PER;
    for (int i = warp; i < A_PER; i += 8) {
        const int a = a0 + i;
        const float ts = audio_ts[b * AA + a];

        // logits l = -(c - ts)^2 / 100, tracked max for stability
        float l[16];
        float m = -1e30f;
#pragma unroll
        for (int k = 0; k < 16; k++) {
            float d = c[k] - ts;
            l[k] = -0.01f * d * d;
            m = fmaxf(m, l[k]);
        }
#pragma unroll
        for (int o = 16; o >= 1; o >>= 1)
            m = fmaxf(m, __shfl_xor_sync(0xffffffffu, m, o));

        float s = 0.0f;
        float e[16];
#pragma unroll
        for (int k = 0; k < 16; k++) {
            e[k] = __expf(l[k] - m);
            s += e[k];
        }
#pragma unroll
        for (int o = 16; o >= 1; o >>= 1)
            s += __shfl_xor_sync(0xffffffffu, s, o);

        const float inv = __frcp_rn(s);
#pragma unroll
        for (int k = 0; k < 16; k++) acc[k] += e[k] * inv;
    }

    // Combine 8 warps' register accumulators in shared memory.
    // t = lane + 32k -> each lane hits a distinct bank, conflict-free per warp.
#pragma unroll
    for (int k = 0; k < 16; k++) atomicAdd(&sWacc[lane + 32 * k], acc[k]);
    __syncthreads();

    for (int i = tid; i < TT; i += 256)
        atomicAdd(&g_W[b * TT + i], sWacc[i]);
}

// Kernel 2: out[b,d] = sum_t hidden[b,d,t] * W[b,t]
// Grid: 512 blocks of 256 threads; each warp computes one (b, d) dot product.
__global__ __launch_bounds__(256) void weighted_reduce_kernel(
    const float* __restrict__ hidden,  // [B, D, T]
    float* __restrict__ out)           // [B, D]
{
    const int b    = blockIdx.x >> 5;        // 32 blocks per batch
    const int dblk = blockIdx.x & 31;        // 8 d per block
    const int tid  = threadIdx.x;
    const int lane = tid & 31;
    const int warp = tid >> 5;

    __shared__ float sw[TT];
    for (int i = tid; i < TT; i += 256) sw[i] = g_W[b * TT + i];
    __syncthreads();

    const int d = dblk * 8 + warp;
    const float* h = hidden + ((size_t)b * DD + d) * TT;

    float s = 0.0f;
#pragma unroll
    for (int k = 0; k < 16; k++) {
        const int t = lane + 32 * k;
        s += h[t] * sw[t];
    }
#pragma unroll
    for (int o = 16; o >= 1; o >>= 1)
        s += __shfl_xor_sync(0xffffffffu, s, o);

    if (lane == 0) out[b * DD + d] = s;
}

extern "C" void kernel_launch(void* const* d_in, const int* in_sizes, int n_in,
                              void* d_out, int out_size) {
    const float* hidden   = (const float*)d_in[0];  // [B, D, T] f32
    const float* centers  = (const float*)d_in[1];  // [B, T]    f32
    const float* audio_ts = (const float*)d_in[2];  // [B, A]    f32
    float* out = (float*)d_out;                     // [B, D]    f32

    (void)in_sizes; (void)n_in; (void)out_size;

    zero_W_kernel<<<BB, TT>>>();
    softmax_acc_kernel<<<BB * CHUNKS, 256>>>(centers, audio_ts);
    weighted_reduce_kernel<<<BB * 32, 256>>>(hidden, out);
}

// round 2
// speedup vs baseline: 1.4140x; 1.4140x over previous
#include <cuda_runtime.h>
#include <cuda_bf16.h>

// Problem dims (fixed by the reference)
#define BB 16
#define TT 512     // text tokens
#define AA 4096    // audio frames
#define DD 256     // hidden dim
#define NCHUNK 8               // a-chunks per batch
#define A_PER (AA / NCHUNK)    // 512 audio frames per block
#define KMAX 8                 // max 256-token window (8 * 32)

// -(1/TEMP^2) * log2(e):  exp(-d^2/100) == exp2(d^2 * KNEG)
#define KNEG (-0.014426950408889634f)

// Per-chunk partial token weights. Fully rewritten every launch (no pre-zero).
__device__ float g_Wpart[BB * NCHUNK * TT];

__device__ __forceinline__ float ex2a(float x) {
    float y; asm("ex2.approx.ftz.f32 %0, %1;" : "=f"(y) : "f"(x)); return y;
}
__device__ __forceinline__ float rcpa(float x) {
    float y; asm("rcp.approx.ftz.f32 %0, %1;" : "=f"(y) : "f"(x)); return y;
}

// Frame loop templated on K (number of 32-token groups in this block's window).
template <int K>
__device__ __forceinline__ void frame_loop(
    const float* __restrict__ sc, int tlo, int thi,
    const float* __restrict__ ats,  // audio_ts + b*AA + a0
    float* __restrict__ sp,         // [8][256] per-warp partials
    int warp, int lane)
{
    float c[K], acc[K];
#pragma unroll
    for (int k = 0; k < K; k++) {
        int t = tlo + lane + 32 * k;
        c[k] = (t < thi) ? sc[t] : 3.0e7f;  // pad -> exp2 underflows to 0
        acc[k] = 0.0f;
    }

    for (int i = warp; i < A_PER; i += 8) {
        const float ts = __ldg(ats + i);
        float e[K];
        float s = 0.0f;
#pragma unroll
        for (int k = 0; k < K; k++) {
            float d = c[k] - ts;
            e[k] = ex2a(d * (d * KNEG));
            s += e[k];
        }
#pragma unroll
        for (int o = 16; o >= 1; o >>= 1)
            s += __shfl_xor_sync(0xffffffffu, s, o);
        const float inv = rcpa(s);
#pragma unroll
        for (int k = 0; k < K; k++) acc[k] = fmaf(e[k], inv, acc[k]);
    }

#pragma unroll
    for (int k = 0; k < K; k++) sp[warp * 256 + lane + 32 * k] = acc[k];
#pragma unroll
    for (int k = K; k < KMAX; k++) sp[warp * 256 + lane + 32 * k] = 0.0f;
}

// Kernel A: windowed softmax-weight accumulation into per-chunk partials.
// Grid: BB*NCHUNK = 128 blocks, 256 threads (8 warps), warp-per-frame.
__global__ __launch_bounds__(256) void softmax_acc_kernel(
    const float* __restrict__ centers,   // [B, T]
    const float* __restrict__ audio_ts)  // [B, A]
{
    const int b     = blockIdx.x >> 3;
    const int chunk = blockIdx.x & 7;
    const int tid   = threadIdx.x;
    const int lane  = tid & 31;
    const int warp  = tid >> 5;

    __shared__ float sc[TT];
    __shared__ float sp[8 * 256];
    __shared__ int   sb[4];

    for (int i = tid; i < TT; i += 256) sc[i] = centers[b * TT + i];
    __syncthreads();

    const float a0 = (float)(chunk * A_PER);
    const float a1 = a0 + (float)(A_PER - 1);

    if (tid < 4) {
        float tgt = (tid == 0) ? a0 - 96.0f
                  : (tid == 1) ? a0
                  : (tid == 2) ? a1
                  :              a1 + 96.0f;
        int lo = 0, hi = TT;
        while (lo < hi) { int mid = (lo + hi) >> 1; if (sc[mid] < tgt) lo = mid + 1; else hi = mid; }
        sb[tid] = lo;
    }
    __syncthreads();

    const int lb = sb[0], p = sb[1], q = sb[2], ub = sb[3];
    int tlo = min(lb, (p > 0) ? p - 1 : 0);
    int thi = max(ub, (q < TT) ? q + 1 : q);
    thi = min(thi, TT);
    thi = min(thi, tlo + 32 * KMAX);  // hard cap: 256-token window
    const int K = (thi - tlo + 31) >> 5;

    const float* ats = audio_ts + b * AA + chunk * A_PER;

    switch (K) {
        case 1: frame_loop<1>(sc, tlo, thi, ats, sp, warp, lane); break;
        case 2: frame_loop<2>(sc, tlo, thi, ats, sp, warp, lane); break;
        case 3: frame_loop<3>(sc, tlo, thi, ats, sp, warp, lane); break;
        case 4: frame_loop<4>(sc, tlo, thi, ats, sp, warp, lane); break;
        case 5: frame_loop<5>(sc, tlo, thi, ats, sp, warp, lane); break;
        case 6: frame_loop<6>(sc, tlo, thi, ats, sp, warp, lane); break;
        case 7: frame_loop<7>(sc, tlo, thi, ats, sp, warp, lane); break;
        default: frame_loop<8>(sc, tlo, thi, ats, sp, warp, lane); break;
    }
    __syncthreads();

    // Cross-warp combine + full (dense) partial write: every t gets a value.
    float* wp = g_Wpart + (b * NCHUNK + chunk) * TT;
    for (int t = tid; t < TT; t += 256) {
        int j = t - tlo;
        float v = 0.0f;
        if (j >= 0 && t < thi) {
#pragma unroll
            for (int w = 0; w < 8; w++) v += sp[w * 256 + j];
        }
        wp[t] = v;
    }
}

// Kernel B: W[b,t] = sum_chunk partials;  out[b,d] = sum_t hidden[b,d,t] * W[b,t]
// Grid: BB*16 = 256 blocks, 256 threads; block covers 16 d's, warp does 2.
__global__ __launch_bounds__(256) void weighted_reduce_kernel(
    const float* __restrict__ hidden,  // [B, D, T]
    float* __restrict__ out)           // [B, D]
{
    const int b    = blockIdx.x >> 4;
    const int dg   = blockIdx.x & 15;
    const int tid  = threadIdx.x;
    const int lane = tid & 31;
    const int warp = tid >> 5;

    __shared__ float w[TT];
    for (int t = tid; t < TT; t += 256) {
        float v = 0.0f;
#pragma unroll
        for (int ch = 0; ch < NCHUNK; ch++)
            v += g_Wpart[(b * NCHUNK + ch) * TT + t];
        w[t] = v;
    }
    __syncthreads();

#pragma unroll
    for (int j = 0; j < 2; j++) {
        const int d = dg * 16 + warp * 2 + j;
        const float* h = hidden + ((size_t)(b * DD + d)) * TT;
        float s = 0.0f;
#pragma unroll
        for (int k = 0; k < 16; k++) {
            const int t = lane + 32 * k;
            s = fmaf(__ldg(h + t), w[t], s);
        }
#pragma unroll
        for (int o = 16; o >= 1; o >>= 1)
            s += __shfl_xor_sync(0xffffffffu, s, o);
        if (lane == 0) out[b * DD + d] = s;
    }
}

extern "C" void kernel_launch(void* const* d_in, const int* in_sizes, int n_in,
                              void* d_out, int out_size) {
    const float* hidden   = (const float*)d_in[0];  // [B, D, T] f32
    const float* centers  = (const float*)d_in[1];  // [B, T]    f32
    const float* audio_ts = (const float*)d_in[2];  // [B, A]    f32
    float* out = (float*)d_out;                     // [B, D]    f32

    (void)in_sizes; (void)n_in; (void)out_size;

    softmax_acc_kernel<<<BB * NCHUNK, 256>>>(centers, audio_ts);
    weighted_reduce_kernel<<<BB * 16, 256>>>(hidden, out);
}

// round 3
// speedup vs baseline: 1.8294x; 1.2937x over previous
#include <cuda_runtime.h>
#include <cuda_bf16.h>

// Problem dims (fixed by the reference)
#define BB 16
#define TT 512     // text tokens
#define AA 4096    // audio frames
#define DD 256     // hidden dim
#define NCHUNK 64              // a-chunks per batch
#define A_PER (AA / NCHUNK)    // 64 audio frames per block
#define KMAX 8                 // hard cap: 256-token window

// -(1/TEMP^2) * log2(e):  exp(-d^2/100) == exp2(d^2 * KNEG)
#define KNEG (-0.014426950408889634f)

// Accumulated token weights W[b][t]; zeroed by Z each launch, atomically
// accumulated by A, consumed by B.
__device__ float g_W[BB * TT];

__device__ __forceinline__ float ex2a(float x) {
    float y; asm("ex2.approx.ftz.f32 %0, %1;" : "=f"(y) : "f"(x)); return y;
}
__device__ __forceinline__ float rcpa(float x) {
    float y; asm("rcp.approx.ftz.f32 %0, %1;" : "=f"(y) : "f"(x)); return y;
}

// Kernel Z: zero g_W (8192 floats). 16 blocks x 128 threads x float4.
__global__ void zero_W_kernel() {
    ((float4*)g_W)[blockIdx.x * 128 + threadIdx.x] = make_float4(0.f, 0.f, 0.f, 0.f);
}

// Frame loop templated on K (number of 32-token groups in this block's window).
template <int K>
__device__ __forceinline__ void frame_loop(
    const float* __restrict__ sc, int tlo, int thi,
    const float* __restrict__ ats,  // audio_ts + b*AA + a0
    float* __restrict__ sp,         // [8][256] per-warp partials
    int warp, int lane)
{
    float c[K], acc[K];
#pragma unroll
    for (int k = 0; k < K; k++) {
        int t = tlo + lane + 32 * k;
        c[k] = (t < thi) ? sc[t] : 3.0e7f;  // pad -> exp2 underflows to 0
        acc[k] = 0.0f;
    }

#pragma unroll 2
    for (int i = warp; i < A_PER; i += 8) {
        const float ts = __ldg(ats + i);
        float e[K];
        float s = 0.0f;
#pragma unroll
        for (int k = 0; k < K; k++) {
            float d = c[k] - ts;
            e[k] = ex2a(d * (d * KNEG));
            s += e[k];
        }
#pragma unroll
        for (int o = 16; o >= 1; o >>= 1)
            s += __shfl_xor_sync(0xffffffffu, s, o);
        const float inv = rcpa(s);
#pragma unroll
        for (int k = 0; k < K; k++) acc[k] = fmaf(e[k], inv, acc[k]);
    }

#pragma unroll
    for (int k = 0; k < K; k++) sp[warp * 256 + lane + 32 * k] = acc[k];
}

// Kernel A: windowed softmax-weight accumulation, atomicAdd into g_W.
// Grid: BB*NCHUNK = 1024 blocks, 256 threads (8 warps), warp-per-frame.
__global__ __launch_bounds__(256) void softmax_acc_kernel(
    const float* __restrict__ centers,   // [B, T]
    const float* __restrict__ audio_ts)  // [B, A]
{
    const int b     = blockIdx.x >> 6;
    const int chunk = blockIdx.x & 63;
    const int tid   = threadIdx.x;
    const int lane  = tid & 31;
    const int warp  = tid >> 5;

    __shared__ float sc[TT];
    __shared__ float sp[8 * 256];
    __shared__ int   sb[4];

    for (int i = tid; i < TT; i += 256) sc[i] = centers[b * TT + i];
    __syncthreads();

    const float a0 = (float)(chunk * A_PER);
    const float a1 = a0 + (float)(A_PER - 1);

    if (tid < 4) {
        float tgt = (tid == 0) ? a0 - 80.0f
                  : (tid == 1) ? a0
                  : (tid == 2) ? a1
                  :              a1 + 80.0f;
        int lo = 0, hi = TT;
        while (lo < hi) { int mid = (lo + hi) >> 1; if (sc[mid] < tgt) lo = mid + 1; else hi = mid; }
        sb[tid] = lo;
    }
    __syncthreads();

    const int lb = sb[0], p = sb[1], q = sb[2], ub = sb[3];
    int tlo = min(lb, (p > 0) ? p - 1 : 0);
    int thi = max(ub, (q < TT) ? q + 1 : q);
    thi = min(thi, TT);
    thi = min(thi, tlo + 32 * KMAX);  // hard cap
    const int K = (thi - tlo + 31) >> 5;

    const float* ats = audio_ts + b * AA + chunk * A_PER;

    switch (K) {
        case 1: frame_loop<1>(sc, tlo, thi, ats, sp, warp, lane); break;
        case 2: frame_loop<2>(sc, tlo, thi, ats, sp, warp, lane); break;
        case 3: frame_loop<3>(sc, tlo, thi, ats, sp, warp, lane); break;
        case 4: frame_loop<4>(sc, tlo, thi, ats, sp, warp, lane); break;
        case 5: frame_loop<5>(sc, tlo, thi, ats, sp, warp, lane); break;
        case 6: frame_loop<6>(sc, tlo, thi, ats, sp, warp, lane); break;
        case 7: frame_loop<7>(sc, tlo, thi, ats, sp, warp, lane); break;
        default: frame_loop<8>(sc, tlo, thi, ats, sp, warp, lane); break;
    }
    __syncthreads();

    // Cross-warp combine + one atomicAdd per window token.
    const int W = thi - tlo;
    for (int j = tid; j < W; j += 256) {
        float v = 0.0f;
#pragma unroll
        for (int w = 0; w < 8; w++) v += sp[w * 256 + j];
        atomicAdd(&g_W[b * TT + tlo + j], v);
    }
}

// Kernel B: out[b,d] = sum_t hidden[b,d,t] * W[b,t]
// Grid: 512 blocks x 256 threads; warp-per-row, float4 loads.
__global__ __launch_bounds__(256) void weighted_reduce_kernel(
    const float* __restrict__ hidden,  // [B, D, T]
    float* __restrict__ out)           // [B, D]
{
    const int b    = blockIdx.x >> 5;   // 32 blocks per batch
    const int dblk = blockIdx.x & 31;   // 8 d per block (warp per d)
    const int tid  = threadIdx.x;
    const int lane = tid & 31;
    const int warp = tid >> 5;

    __shared__ float4 w4[TT / 4];
    if (tid < TT / 4) w4[tid] = ((const float4*)(g_W + b * TT))[tid];
    __syncthreads();

    const int d = dblk * 8 + warp;
    const float4* h4 = (const float4*)(hidden + ((size_t)(b * DD + d)) * TT);

    float s = 0.0f;
#pragma unroll
    for (int k = 0; k < 4; k++) {
        const int j = lane + 32 * k;  // float4 index within the 512-float row
        float4 h = __ldg(h4 + j);
        float4 w = w4[j];
        s = fmaf(h.x, w.x, s);
        s = fmaf(h.y, w.y, s);
        s = fmaf(h.z, w.z, s);
        s = fmaf(h.w, w.w, s);
    }
#pragma unroll
    for (int o = 16; o >= 1; o >>= 1)
        s += __shfl_xor_sync(0xffffffffu, s, o);

    if (lane == 0) out[b * DD + d] = s;
}

extern "C" void kernel_launch(void* const* d_in, const int* in_sizes, int n_in,
                              void* d_out, int out_size) {
    const float* hidden   = (const float*)d_in[0];  // [B, D, T] f32
    const float* centers  = (const float*)d_in[1];  // [B, T]    f32
    const float* audio_ts = (const float*)d_in[2];  // [B, A]    f32
    float* out = (float*)d_out;                     // [B, D]    f32

    (void)in_sizes; (void)n_in; (void)out_size;

    zero_W_kernel<<<16, 128>>>();
    softmax_acc_kernel<<<BB * NCHUNK, 256>>>(centers, audio_ts);
    weighted_reduce_kernel<<<BB * 32, 256>>>(hidden, out);
}